// round 6
// baseline (speedup 1.0000x reference)
#include <cuda_runtime.h>

// Batched 512-point complex forward DFT (== reference complex matmul by
// W[h,j] = exp(-2*pi*i*j*h/512)), computed as a radix-8^3 FFT.
//
// R5: 2 rows per thread. Doubles LDG MLP, halves barriers per FFT, and
// amortizes the twiddle-power chains across both rows. Same conflict-free
// layouts and fully-coalesced output as R4.

#define NROWS 32768
#define FPB 4              // FFT slot groups per block
#define RPT 2              // rows (FFTs) per thread
#define TPF 64             // threads per FFT
#define BLOCK (FPB * TPF)  // 256 threads, 8 FFTs per block
#define BUFSZ 576          // stage1 stride 72 * 8
#define S2 66              // stage-2 store stride (2 mod 16 -> conflict-free)

__device__ __forceinline__ float2 cadd(float2 a, float2 b) { return make_float2(a.x + b.x, a.y + b.y); }
__device__ __forceinline__ float2 csub(float2 a, float2 b) { return make_float2(a.x - b.x, a.y - b.y); }
__device__ __forceinline__ float2 cmul(float2 a, float2 b) {
    return make_float2(fmaf(a.x, b.x, -a.y * b.y), fmaf(a.x, b.y, a.y * b.x));
}
__device__ __forceinline__ float2 mul_mi(float2 a) { return make_float2(a.y, -a.x); }  // *(-i)

// 8-point DFT: A[k] = sum_j a[j] * W8^(jk),  W8 = exp(-2*pi*i/8)
__device__ __forceinline__ void dft8(const float2* a, float2* A) {
    float2 e0p = cadd(a[0], a[4]), e0m = csub(a[0], a[4]);
    float2 e1p = cadd(a[2], a[6]), e1m = csub(a[2], a[6]);
    float2 E0 = cadd(e0p, e1p), E2 = csub(e0p, e1p);
    float2 mie = mul_mi(e1m);
    float2 E1 = cadd(e0m, mie);
    float2 E3 = csub(e0m, mie);

    float2 o0p = cadd(a[1], a[5]), o0m = csub(a[1], a[5]);
    float2 o1p = cadd(a[3], a[7]), o1m = csub(a[3], a[7]);
    float2 O0 = cadd(o0p, o1p), O2 = csub(o0p, o1p);
    float2 mio = mul_mi(o1m);
    float2 O1 = cadd(o0m, mio);
    float2 O3 = csub(o0m, mio);

    const float c = 0.70710678118654752440f;  // sqrt(2)/2
    float2 t0 = O0;
    float2 t1 = make_float2(c * (O1.x + O1.y), c * (O1.y - O1.x));   // (c,-c)*O1
    float2 t2 = mul_mi(O2);                                          // (0,-1)*O2
    float2 t3 = make_float2(c * (O3.y - O3.x), -c * (O3.x + O3.y));  // (-c,-c)*O3

    A[0] = cadd(E0, t0); A[4] = csub(E0, t0);
    A[1] = cadd(E1, t1); A[5] = csub(E1, t1);
    A[2] = cadd(E2, t2); A[6] = csub(E2, t2);
    A[3] = cadd(E3, t3); A[7] = csub(E3, t3);
}

__global__ __launch_bounds__(BLOCK, 4)
void fft512_kernel(const float* __restrict__ xre, const float* __restrict__ xim,
                   const float* __restrict__ wre, const float* __restrict__ wim,
                   float* __restrict__ out) {
    __shared__ float2 tw2[512];                // W512^a exact base twiddles
    __shared__ float2 tws2[64];                // tws2[i] = W512^(8*(i&7))
    __shared__ float2 buf[FPB * RPT][BUFSZ];   // 8 FFT slots

    const int tid = threadIdx.x;
    const int f = tid >> 6;       // slot group (0..3)
    const int t = tid & 63;       // thread within FFT
    const int rowA = blockIdx.x * (FPB * RPT) + f;
    const int rowB = rowA + FPB;
    const int sA = f, sB = f + FPB;

    // Exact twiddles from w table row 1: W^a = (w_re[512+a], w_im[512+a])
    #pragma unroll
    for (int i = tid; i < 512; i += BLOCK)
        tw2[i] = make_float2(wre[512 + i], wim[512 + i]);
    if (tid < 64)
        tws2[tid] = make_float2(wre[512 + 8 * (tid & 7)], wim[512 + 8 * (tid & 7)]);

    const float* xrA = xre + (size_t)rowA * 512;
    const float* xiA = xim + (size_t)rowA * 512;
    const float* xrB = xre + (size_t)rowB * 512;
    const float* xiB = xim + (size_t)rowB * 512;

    float2 a0[8], a1[8], A0[8], A1[8];
    // Stage 1 inputs for both rows up front: 32 independent LDG.32 in flight
    #pragma unroll
    for (int j2 = 0; j2 < 8; j2++) {
        a0[j2] = make_float2(xrA[t + 64 * j2], xiA[t + 64 * j2]);
        a1[j2] = make_float2(xrB[t + 64 * j2], xiB[t + 64 * j2]);
    }

    __syncthreads();  // twiddles ready

    // ---- Stage 1: DFT8 over j2 -> digit h0; twiddle W512^(t*h0); [h0*72+t] ----
    dft8(a0, A0);
    dft8(a1, A1);
    {
        float2 wb = tw2[t];   // conflict-free LDS.64, shared by both rows
        float2 w = wb;
        #pragma unroll
        for (int h0 = 1; h0 < 8; h0++) {
            A0[h0] = cmul(A0[h0], w);
            A1[h0] = cmul(A1[h0], w);
            if (h0 < 7) w = cmul(w, wb);
        }
    }
    #pragma unroll
    for (int h0 = 0; h0 < 8; h0++) {
        buf[sA][h0 * 72 + t] = A0[h0];
        buf[sB][h0 * 72 + t] = A1[h0];
    }
    __syncthreads();

    // ---- Stage 2: thread (h0 = t>>3, j1a = t&7); DFT8 over j1b -> h10;
    //      twiddle W512^(8*j1a*h10); store [j1a*66 + 8*h10 + h0] ----
    {
        const int h0 = t >> 3;
        const int j1a = t & 7;
        #pragma unroll
        for (int j1b = 0; j1b < 8; j1b++) {
            int idx = h0 * 72 + j1a + 8 * j1b;
            a0[j1b] = buf[sA][idx];
            a1[j1b] = buf[sB][idx];
        }
        __syncthreads();  // reads done before buffer reuse

        dft8(a0, A0);
        dft8(a1, A1);
        float2 wb = tws2[t];  // = W^(8*j1a), conflict-free
        float2 w = wb;
        #pragma unroll
        for (int h10 = 1; h10 < 8; h10++) {
            A0[h10] = cmul(A0[h10], w);
            A1[h10] = cmul(A1[h10], w);
            if (h10 < 7) w = cmul(w, wb);
        }
        #pragma unroll
        for (int h10 = 0; h10 < 8; h10++) {
            int idx = j1a * S2 + 8 * h10 + h0;
            buf[sA][idx] = A0[h10];
            buf[sB][idx] = A1[h10];
        }
    }
    __syncthreads();

    // ---- Stage 3: thread t owns (h0 = t&7, h10 = t>>3); stage-2 layout index
    //      8*h10 + h0 == t -> consecutive loads, fully coalesced stores ----
    {
        #pragma unroll
        for (int j = 0; j < 8; j++) {
            a0[j] = buf[sA][j * S2 + t];
            a1[j] = buf[sB][j * S2 + t];
        }

        dft8(a0, A0);
        dft8(a1, A1);

        // h = t + 64*h11: 256B contiguous per warp per store
        float2* oA = reinterpret_cast<float2*>(out) + (size_t)rowA * 512;
        float2* oB = reinterpret_cast<float2*>(out) + (size_t)rowB * 512;
        #pragma unroll
        for (int h11 = 0; h11 < 8; h11++) {
            oA[t + 64 * h11] = A0[h11];
            oB[t + 64 * h11] = A1[h11];
        }
    }
}

extern "C" void kernel_launch(void* const* d_in, const int* in_sizes, int n_in,
                              void* d_out, int out_size) {
    const float* x_re = (const float*)d_in[0];
    const float* x_im = (const float*)d_in[1];
    const float* w_re = (const float*)d_in[2];
    const float* w_im = (const float*)d_in[3];
    float* out = (float*)d_out;

    dim3 grid(NROWS / (FPB * RPT));  // 4096 blocks
    dim3 block(BLOCK);               // 256 threads = 8 FFTs
    fft512_kernel<<<grid, block>>>(x_re, x_im, w_re, w_im, out);
}